// round 2
// baseline (speedup 1.0000x reference)
#include <cuda_runtime.h>
#include <cstdint>
#include <math.h>

// Problem constants (B, L, H, E) = (4, 2048, 16, 64), qkv: (B, L, 3, H, E) fp32
#define BB 4
#define LL 2048
#define HH 16
#define EE 64

#define BQ 64        // Q rows per CTA (16 per warp x 4 warps)
#define BK 64        // K/V rows per tile
#define NWARP 4
#define NTHREAD 128

#define SQ_STRIDE 68 // rows indexed by grp -> stride % 32 == 4 -> conflict free
#define SK_STRIDE 68
#define SV_STRIDE 72 // rows indexed by tq  -> stride % 32 == 8 -> conflict free

#define NEG_INF (-1e30f)

__device__ __forceinline__ unsigned f2tf(float x) {
    unsigned r;
    asm("cvt.rna.tf32.f32 %0, %1;" : "=r"(r) : "f"(x));
    return r;
}

__device__ __forceinline__ void mma_tf32(float c[4], const unsigned a[4], unsigned b0, unsigned b1) {
    asm volatile(
        "mma.sync.aligned.m16n8k8.row.col.f32.tf32.tf32.f32 "
        "{%0,%1,%2,%3},{%4,%5,%6,%7},{%8,%9},{%0,%1,%2,%3};"
        : "+f"(c[0]), "+f"(c[1]), "+f"(c[2]), "+f"(c[3])
        : "r"(a[0]), "r"(a[1]), "r"(a[2]), "r"(a[3]), "r"(b0), "r"(b1));
}

__global__ __launch_bounds__(NTHREAD, 2)
void fa_tf32_kernel(const float* __restrict__ qkv, float* __restrict__ out) {
    extern __shared__ float smem[];
    float* sQ = smem;                         // 64 x 68 (reused as sP after Q frags read)
    float* sK = sQ + BQ * SQ_STRIDE;          // 64 x 68
    float* sV = sK + BK * SK_STRIDE;          // 64 x 72

    const int tid  = threadIdx.x;
    const int w    = tid >> 5;
    const int lane = tid & 31;
    const int grp  = lane >> 2;   // 0..7
    const int tq   = lane & 3;    // 0..3

    // reverse q-tile order so heaviest (most causal work) CTAs launch first
    const int qi = gridDim.x - 1 - blockIdx.x;
    const int bh = blockIdx.y;
    const int b  = bh / HH;
    const int h  = bh % HH;
    const int q0 = qi * BQ;

    const size_t HE  = (size_t)HH * EE;   // 1024
    const size_t ROW = 3 * HE;            // 3072 floats between consecutive tokens

    // ---- load Q tile (pre-scaled by 1/sqrt(E) = 0.125 exactly, rounded to tf32) ----
    {
        const float* gq = qkv + ((size_t)(b * LL + q0) * 3) * HE + (size_t)h * EE;
        for (int it = tid; it < BQ * (EE / 4); it += NTHREAD) {
            int r = it >> 4;
            int c = (it & 15) << 2;
            float4 v = *(const float4*)(gq + (size_t)r * ROW + c);
            v.x = __uint_as_float(f2tf(v.x * 0.125f));
            v.y = __uint_as_float(f2tf(v.y * 0.125f));
            v.z = __uint_as_float(f2tf(v.z * 0.125f));
            v.w = __uint_as_float(f2tf(v.w * 0.125f));
            *(float4*)(sQ + r * SQ_STRIDE + c) = v;
        }
    }
    __syncthreads();

    // ---- Q fragments into registers (warp reads only its own 16 rows) ----
    unsigned qa[8][4];
    {
        const float* r0 = sQ + (w * 16 + grp) * SQ_STRIDE;
        const float* r1 = r0 + 8 * SQ_STRIDE;
        #pragma unroll
        for (int k = 0; k < 8; ++k) {
            qa[k][0] = __float_as_uint(r0[k * 8 + tq]);
            qa[k][1] = __float_as_uint(r1[k * 8 + tq]);
            qa[k][2] = __float_as_uint(r0[k * 8 + tq + 4]);
            qa[k][3] = __float_as_uint(r1[k * 8 + tq + 4]);
        }
    }

    float o[8][4];
    #pragma unroll
    for (int n = 0; n < 8; ++n) { o[n][0] = 0.f; o[n][1] = 0.f; o[n][2] = 0.f; o[n][3] = 0.f; }
    float m0 = NEG_INF, m1 = NEG_INF;
    float l0 = 0.f, l1 = 0.f;

    for (int j = 0; j <= qi; ++j) {
        __syncthreads();  // previous tile's consumers done before overwriting sK/sV

        // ---- load K, V tile j (tf32-rounded) ----
        {
            const float* gk = qkv + ((size_t)(b * LL + j * BK) * 3 + 1) * HE + (size_t)h * EE;
            const float* gv = gk + HE;
            for (int it = tid; it < BK * (EE / 4); it += NTHREAD) {
                int r = it >> 4;
                int c = (it & 15) << 2;
                float4 v = *(const float4*)(gk + (size_t)r * ROW + c);
                v.x = __uint_as_float(f2tf(v.x));
                v.y = __uint_as_float(f2tf(v.y));
                v.z = __uint_as_float(f2tf(v.z));
                v.w = __uint_as_float(f2tf(v.w));
                *(float4*)(sK + r * SK_STRIDE + c) = v;
            }
            for (int it = tid; it < BK * (EE / 4); it += NTHREAD) {
                int r = it >> 4;
                int c = (it & 15) << 2;
                float4 v = *(const float4*)(gv + (size_t)r * ROW + c);
                v.x = __uint_as_float(f2tf(v.x));
                v.y = __uint_as_float(f2tf(v.y));
                v.z = __uint_as_float(f2tf(v.z));
                v.w = __uint_as_float(f2tf(v.w));
                *(float4*)(sV + r * SV_STRIDE + c) = v;
            }
        }
        __syncthreads();

        // ---- S = Q * K^T (already scaled), 16x64 per warp ----
        float sc[8][4];
        #pragma unroll
        for (int n = 0; n < 8; ++n) { sc[n][0] = 0.f; sc[n][1] = 0.f; sc[n][2] = 0.f; sc[n][3] = 0.f; }

        #pragma unroll
        for (int n = 0; n < 8; ++n) {
            const float* krow = sK + (n * 8 + grp) * SK_STRIDE;
            #pragma unroll
            for (int k = 0; k < 8; ++k) {
                unsigned b0 = __float_as_uint(krow[k * 8 + tq]);
                unsigned b1 = __float_as_uint(krow[k * 8 + tq + 4]);
                mma_tf32(sc[n], qa[k], b0, b1);
            }
        }

        // ---- causal mask (only the diagonal tile) ----
        if (j == qi) {
            const int r0 = w * 16 + grp;
            const int r1 = r0 + 8;
            #pragma unroll
            for (int n = 0; n < 8; ++n) {
                int c0 = n * 8 + tq * 2;
                if (c0 > r0)     sc[n][0] = NEG_INF;
                if (c0 + 1 > r0) sc[n][1] = NEG_INF;
                if (c0 > r1)     sc[n][2] = NEG_INF;
                if (c0 + 1 > r1) sc[n][3] = NEG_INF;
            }
        }

        // ---- online softmax ----
        float mx0 = NEG_INF, mx1 = NEG_INF;
        #pragma unroll
        for (int n = 0; n < 8; ++n) {
            mx0 = fmaxf(mx0, fmaxf(sc[n][0], sc[n][1]));
            mx1 = fmaxf(mx1, fmaxf(sc[n][2], sc[n][3]));
        }
        mx0 = fmaxf(mx0, __shfl_xor_sync(0xffffffffu, mx0, 1));
        mx0 = fmaxf(mx0, __shfl_xor_sync(0xffffffffu, mx0, 2));
        mx1 = fmaxf(mx1, __shfl_xor_sync(0xffffffffu, mx1, 1));
        mx1 = fmaxf(mx1, __shfl_xor_sync(0xffffffffu, mx1, 2));

        float mn0 = fmaxf(m0, mx0);
        float mn1 = fmaxf(m1, mx1);
        float a0 = __expf(m0 - mn0);
        float a1 = __expf(m1 - mn1);
        m0 = mn0; m1 = mn1;

        float s0 = 0.f, s1 = 0.f;
        #pragma unroll
        for (int n = 0; n < 8; ++n) {
            sc[n][0] = __expf(sc[n][0] - mn0); s0 += sc[n][0];
            sc[n][1] = __expf(sc[n][1] - mn0); s0 += sc[n][1];
            sc[n][2] = __expf(sc[n][2] - mn1); s1 += sc[n][2];
            sc[n][3] = __expf(sc[n][3] - mn1); s1 += sc[n][3];
        }
        s0 += __shfl_xor_sync(0xffffffffu, s0, 1);
        s0 += __shfl_xor_sync(0xffffffffu, s0, 2);
        s1 += __shfl_xor_sync(0xffffffffu, s1, 1);
        s1 += __shfl_xor_sync(0xffffffffu, s1, 2);
        l0 = l0 * a0 + s0;
        l1 = l1 * a1 + s1;

        #pragma unroll
        for (int n = 0; n < 8; ++n) {
            o[n][0] *= a0; o[n][1] *= a0;
            o[n][2] *= a1; o[n][3] *= a1;
        }

        // ---- P -> smem (warp-private rows of sQ region), tf32-rounded ----
        {
            float* p0 = sQ + (w * 16 + grp) * SQ_STRIDE;
            float* p1 = p0 + 8 * SQ_STRIDE;
            #pragma unroll
            for (int n = 0; n < 8; ++n) {
                int c = n * 8 + tq * 2;
                float2 v0 = make_float2(__uint_as_float(f2tf(sc[n][0])),
                                        __uint_as_float(f2tf(sc[n][1])));
                float2 v1 = make_float2(__uint_as_float(f2tf(sc[n][2])),
                                        __uint_as_float(f2tf(sc[n][3])));
                *(float2*)(p0 + c) = v0;
                *(float2*)(p1 + c) = v1;
            }
        }
        __syncwarp();

        // ---- O += P * V ----
        {
            const float* p0 = sQ + (w * 16 + grp) * SQ_STRIDE;
            const float* p1 = p0 + 8 * SQ_STRIDE;
            #pragma unroll
            for (int k = 0; k < 8; ++k) {
                unsigned aa[4];
                aa[0] = __float_as_uint(p0[k * 8 + tq]);
                aa[1] = __float_as_uint(p1[k * 8 + tq]);
                aa[2] = __float_as_uint(p0[k * 8 + tq + 4]);
                aa[3] = __float_as_uint(p1[k * 8 + tq + 4]);
                const float* v0 = sV + (k * 8 + tq) * SV_STRIDE;
                const float* v1 = sV + (k * 8 + tq + 4) * SV_STRIDE;
                #pragma unroll
                for (int n = 0; n < 8; ++n) {
                    unsigned b0 = __float_as_uint(v0[n * 8 + grp]);
                    unsigned b1 = __float_as_uint(v1[n * 8 + grp]);
                    mma_tf32(o[n], aa, b0, b1);
                }
            }
        }
        __syncwarp();   // P reads complete before next iteration's P writes
    }

    // ---- epilogue: normalize by l, write out (B, L, H, E) ----
    {
        float inv0 = 1.0f / l0;
        float inv1 = 1.0f / l1;
        const int r0 = q0 + w * 16 + grp;
        const int r1 = r0 + 8;
        float* o0 = out + ((size_t)(b * LL + r0) * HH + h) * EE;
        float* o1 = out + ((size_t)(b * LL + r1) * HH + h) * EE;
        #pragma unroll
        for (int n = 0; n < 8; ++n) {
            int c = n * 8 + tq * 2;
            *(float2*)(o0 + c) = make_float2(o[n][0] * inv0, o[n][1] * inv0);
            *(float2*)(o1 + c) = make_float2(o[n][2] * inv1, o[n][3] * inv1);
        }
    }
}

extern "C" void kernel_launch(void* const* d_in, const int* in_sizes, int n_in,
                              void* d_out, int out_size) {
    const float* qkv = (const float*)d_in[0];
    float* out = (float*)d_out;

    const int smem_bytes = (BQ * SQ_STRIDE + BK * SK_STRIDE + BK * SV_STRIDE) * (int)sizeof(float);
    cudaFuncSetAttribute(fa_tf32_kernel, cudaFuncAttributeMaxDynamicSharedMemorySize, smem_bytes);

    dim3 grid(LL / BQ, BB * HH);   // (32, 64)
    fa_tf32_kernel<<<grid, NTHREAD, smem_bytes>>>(qkv, out);
}

// round 3
// speedup vs baseline: 1.3580x; 1.3580x over previous
#include <cuda_runtime.h>
#include <cstdint>
#include <math.h>

// (B, L, H, E) = (4, 2048, 16, 64), qkv: (B, L, 3, H, E) fp32
#define BB 4
#define LL 2048
#define HH 16
#define EE 64

#define BQ 64        // Q rows per CTA (16 per warp x 4 warps)
#define BK 32        // K/V rows per tile (double buffered)
#define NTHREAD 128

#define SQ_STRIDE 68 // rows indexed by grp -> stride % 32 == 4 -> conflict free
#define SK_STRIDE 68
#define SV_STRIDE 72 // rows indexed by token -> stride % 32 == 8 -> conflict free

#define NEG_INF (-1e30f)

__device__ __forceinline__ unsigned f2tf(float x) {
    unsigned r;
    asm("cvt.rna.tf32.f32 %0, %1;" : "=r"(r) : "f"(x));
    return r;
}

__device__ __forceinline__ void mma_tf32(float c[4], const unsigned a[4], unsigned b0, unsigned b1) {
    asm volatile(
        "mma.sync.aligned.m16n8k8.row.col.f32.tf32.tf32.f32 "
        "{%0,%1,%2,%3},{%4,%5,%6,%7},{%8,%9},{%0,%1,%2,%3};"
        : "+f"(c[0]), "+f"(c[1]), "+f"(c[2]), "+f"(c[3])
        : "r"(a[0]), "r"(a[1]), "r"(a[2]), "r"(a[3]), "r"(b0), "r"(b1));
}

__device__ __forceinline__ void cp16(float* dst_smem, const float* src) {
    unsigned d = (unsigned)__cvta_generic_to_shared(dst_smem);
    asm volatile("cp.async.cg.shared.global [%0], [%1], 16;" :: "r"(d), "l"(src));
}

__global__ __launch_bounds__(NTHREAD, 3)
void fa_tf32_kernel(const float* __restrict__ qkv, float* __restrict__ out) {
    extern __shared__ float smem[];
    float* sQ = smem;                          // 64 x 68 (reused as sP)
    float* sK = sQ + BQ * SQ_STRIDE;           // 2 x 32 x 68
    float* sV = sK + 2 * BK * SK_STRIDE;       // 2 x 32 x 72

    const int tid  = threadIdx.x;
    const int w    = tid >> 5;
    const int lane = tid & 31;
    const int grp  = lane >> 2;   // 0..7
    const int tq   = lane & 3;    // 0..3

    // heaviest q-tiles first
    const int qi = gridDim.x - 1 - blockIdx.x;
    const int bh = blockIdx.y;
    const int b  = bh / HH;
    const int h  = bh % HH;
    const int q0 = qi * BQ;
    const int nkv = 2 * (qi + 1);   // # of 32-row kv tiles

    const size_t HE  = (size_t)HH * EE;   // 1024
    const size_t ROW = 3 * HE;            // 3072

    // ---- load Q tile (pre-scaled by 1/8, tf32-rounded) ----
    {
        const float* gq = qkv + ((size_t)(b * LL + q0) * 3) * HE + (size_t)h * EE;
        for (int it = tid; it < BQ * (EE / 4); it += NTHREAD) {
            int r = it >> 4;
            int c = (it & 15) << 2;
            float4 v = *(const float4*)(gq + (size_t)r * ROW + c);
            v.x = __uint_as_float(f2tf(v.x * 0.125f));
            v.y = __uint_as_float(f2tf(v.y * 0.125f));
            v.z = __uint_as_float(f2tf(v.z * 0.125f));
            v.w = __uint_as_float(f2tf(v.w * 0.125f));
            *(float4*)(sQ + r * SQ_STRIDE + c) = v;
        }
    }

    const float* gkv_base = qkv + ((size_t)b * LL * 3 + 1) * HE + (size_t)h * EE;

    // ---- prefetch kv tile 0 into buffer 0 ----
    {
        const float* gk = gkv_base + (size_t)0 * BK * ROW;
        const float* gv = gk + HE;
        for (int it = tid; it < BK * (EE / 4); it += NTHREAD) {
            int r = it >> 4, c = (it & 15) << 2;
            cp16(sK + r * SK_STRIDE + c, gk + (size_t)r * ROW + c);
        }
        for (int it = tid; it < BK * (EE / 4); it += NTHREAD) {
            int r = it >> 4, c = (it & 15) << 2;
            cp16(sV + r * SV_STRIDE + c, gv + (size_t)r * ROW + c);
        }
    }
    asm volatile("cp.async.commit_group;");

    __syncthreads();   // sQ visible

    // ---- Q fragments to registers (warp-private 16 rows) ----
    unsigned qa[8][4];
    {
        const float* r0 = sQ + (w * 16 + grp) * SQ_STRIDE;
        const float* r1 = r0 + 8 * SQ_STRIDE;
        #pragma unroll
        for (int k = 0; k < 8; ++k) {
            qa[k][0] = __float_as_uint(r0[k * 8 + tq]);
            qa[k][1] = __float_as_uint(r1[k * 8 + tq]);
            qa[k][2] = __float_as_uint(r0[k * 8 + tq + 4]);
            qa[k][3] = __float_as_uint(r1[k * 8 + tq + 4]);
        }
    }

    float o[8][4];
    #pragma unroll
    for (int n = 0; n < 8; ++n) { o[n][0] = 0.f; o[n][1] = 0.f; o[n][2] = 0.f; o[n][3] = 0.f; }
    float m0 = NEG_INF, m1 = NEG_INF;
    float l0 = 0.f, l1 = 0.f;

    for (int j = 0; j < nkv; ++j) {
        // ---- prefetch tile j+1 into buffer (j+1)&1 ----
        if (j + 1 < nkv) {
            const float* gk = gkv_base + (size_t)(j + 1) * BK * ROW;
            const float* gv = gk + HE;
            float* dK = sK + ((j + 1) & 1) * (BK * SK_STRIDE);
            float* dV = sV + ((j + 1) & 1) * (BK * SV_STRIDE);
            for (int it = tid; it < BK * (EE / 4); it += NTHREAD) {
                int r = it >> 4, c = (it & 15) << 2;
                cp16(dK + r * SK_STRIDE + c, gk + (size_t)r * ROW + c);
            }
            for (int it = tid; it < BK * (EE / 4); it += NTHREAD) {
                int r = it >> 4, c = (it & 15) << 2;
                cp16(dV + r * SV_STRIDE + c, gv + (size_t)r * ROW + c);
            }
        }
        asm volatile("cp.async.commit_group;");     // one group per iter (maybe empty)
        asm volatile("cp.async.wait_group 1;");     // tile j's group complete
        __syncthreads();

        const float* cK = sK + (j & 1) * (BK * SK_STRIDE);
        const float* cV = sV + (j & 1) * (BK * SV_STRIDE);

        // ---- S = Q * K^T : 16x32 per warp ----
        float sc[4][4];
        #pragma unroll
        for (int n = 0; n < 4; ++n) { sc[n][0] = 0.f; sc[n][1] = 0.f; sc[n][2] = 0.f; sc[n][3] = 0.f; }

        #pragma unroll
        for (int n = 0; n < 4; ++n) {
            const float* krow = cK + (n * 8 + grp) * SK_STRIDE;
            #pragma unroll
            for (int k = 0; k < 8; ++k) {
                unsigned b0 = f2tf(krow[k * 8 + tq]);
                unsigned b1 = f2tf(krow[k * 8 + tq + 4]);
                mma_tf32(sc[n], qa[k], b0, b1);
            }
        }

        // ---- causal mask (only the last two tiles can cross the diagonal) ----
        if (j >= nkv - 2) {
            const int kb = j * BK;
            const int r0a = q0 + w * 16 + grp;
            const int r1a = r0a + 8;
            #pragma unroll
            for (int n = 0; n < 4; ++n) {
                int c0 = kb + n * 8 + tq * 2;
                if (c0 > r0a)     sc[n][0] = NEG_INF;
                if (c0 + 1 > r0a) sc[n][1] = NEG_INF;
                if (c0 > r1a)     sc[n][2] = NEG_INF;
                if (c0 + 1 > r1a) sc[n][3] = NEG_INF;
            }
        }

        // ---- online softmax ----
        float mx0 = NEG_INF, mx1 = NEG_INF;
        #pragma unroll
        for (int n = 0; n < 4; ++n) {
            mx0 = fmaxf(mx0, fmaxf(sc[n][0], sc[n][1]));
            mx1 = fmaxf(mx1, fmaxf(sc[n][2], sc[n][3]));
        }
        mx0 = fmaxf(mx0, __shfl_xor_sync(0xffffffffu, mx0, 1));
        mx0 = fmaxf(mx0, __shfl_xor_sync(0xffffffffu, mx0, 2));
        mx1 = fmaxf(mx1, __shfl_xor_sync(0xffffffffu, mx1, 1));
        mx1 = fmaxf(mx1, __shfl_xor_sync(0xffffffffu, mx1, 2));

        float mn0 = fmaxf(m0, mx0);
        float mn1 = fmaxf(m1, mx1);
        float a0 = __expf(m0 - mn0);
        float a1 = __expf(m1 - mn1);
        m0 = mn0; m1 = mn1;

        float s0 = 0.f, s1 = 0.f;
        #pragma unroll
        for (int n = 0; n < 4; ++n) {
            sc[n][0] = __expf(sc[n][0] - mn0); s0 += sc[n][0];
            sc[n][1] = __expf(sc[n][1] - mn0); s0 += sc[n][1];
            sc[n][2] = __expf(sc[n][2] - mn1); s1 += sc[n][2];
            sc[n][3] = __expf(sc[n][3] - mn1); s1 += sc[n][3];
        }
        s0 += __shfl_xor_sync(0xffffffffu, s0, 1);
        s0 += __shfl_xor_sync(0xffffffffu, s0, 2);
        s1 += __shfl_xor_sync(0xffffffffu, s1, 1);
        s1 += __shfl_xor_sync(0xffffffffu, s1, 2);
        l0 = l0 * a0 + s0;
        l1 = l1 * a1 + s1;

        #pragma unroll
        for (int n = 0; n < 8; ++n) {
            o[n][0] *= a0; o[n][1] *= a0;
            o[n][2] *= a1; o[n][3] *= a1;
        }

        // ---- P -> smem (warp-private rows of sQ region) ----
        {
            float* p0 = sQ + (w * 16 + grp) * SQ_STRIDE;
            float* p1 = p0 + 8 * SQ_STRIDE;
            #pragma unroll
            for (int n = 0; n < 4; ++n) {
                int c = n * 8 + tq * 2;
                *(float2*)(p0 + c) = make_float2(__uint_as_float(f2tf(sc[n][0])),
                                                 __uint_as_float(f2tf(sc[n][1])));
                *(float2*)(p1 + c) = make_float2(__uint_as_float(f2tf(sc[n][2])),
                                                 __uint_as_float(f2tf(sc[n][3])));
            }
        }
        __syncwarp();

        // ---- O += P * V ----
        {
            const float* p0 = sQ + (w * 16 + grp) * SQ_STRIDE;
            const float* p1 = p0 + 8 * SQ_STRIDE;
            #pragma unroll
            for (int k = 0; k < 4; ++k) {
                unsigned aa[4];
                aa[0] = __float_as_uint(p0[k * 8 + tq]);
                aa[1] = __float_as_uint(p1[k * 8 + tq]);
                aa[2] = __float_as_uint(p0[k * 8 + tq + 4]);
                aa[3] = __float_as_uint(p1[k * 8 + tq + 4]);
                const float* v0 = cV + (k * 8 + tq) * SV_STRIDE;
                const float* v1 = cV + (k * 8 + tq + 4) * SV_STRIDE;
                #pragma unroll
                for (int n = 0; n < 8; ++n) {
                    unsigned b0 = f2tf(v0[n * 8 + grp]);
                    unsigned b1 = f2tf(v1[n * 8 + grp]);
                    mma_tf32(o[n], aa, b0, b1);
                }
            }
        }
        __syncwarp();          // P reads done before next tile's P writes
        __syncthreads();       // kv buffer reads done before it is overwritten
    }

    // ---- epilogue ----
    {
        float inv0 = 1.0f / l0;
        float inv1 = 1.0f / l1;
        const int r0 = q0 + w * 16 + grp;
        const int r1 = r0 + 8;
        float* o0 = out + ((size_t)(b * LL + r0) * HH + h) * EE;
        float* o1 = out + ((size_t)(b * LL + r1) * HH + h) * EE;
        #pragma unroll
        for (int n = 0; n < 8; ++n) {
            int c = n * 8 + tq * 2;
            *(float2*)(o0 + c) = make_float2(o[n][0] * inv0, o[n][1] * inv0);
            *(float2*)(o1 + c) = make_float2(o[n][2] * inv1, o[n][3] * inv1);
        }
    }
}

extern "C" void kernel_launch(void* const* d_in, const int* in_sizes, int n_in,
                              void* d_out, int out_size) {
    const float* qkv = (const float*)d_in[0];
    float* out = (float*)d_out;

    const int smem_bytes = (BQ * SQ_STRIDE + 2 * BK * SK_STRIDE + 2 * BK * SV_STRIDE) * (int)sizeof(float);
    cudaFuncSetAttribute(fa_tf32_kernel, cudaFuncAttributeMaxDynamicSharedMemorySize, smem_bytes);

    dim3 grid(LL / BQ, BB * HH);   // (32, 64)
    fa_tf32_kernel<<<grid, NTHREAD, smem_bytes>>>(qkv, out);
}